// round 14
// baseline (speedup 1.0000x reference)
#include <cuda_runtime.h>
#include <cuda_fp16.h>
#include <cstdint>

#define T_ROLL 32
#define HDIM   1024
#define GDIM   4096
#define NTRAJ  2048
#define NROWS  65536
#define KDIM   1024

#define STAGES 8
#define KCH    32                  // k halves per chunk
#define RB     80                  // smem row stride bytes (32 fp16 = 64B + 16 pad)
#define OP_BYTES (128 * RB)        // 10240
#define OFF_B  OP_BYTES
#define STAGE_BYTES (2 * OP_BYTES)           // 20480
#define MB_OFF (STAGES * STAGE_BYTES)        // 163840
#define SMEM_TOTAL (MB_OFF + 256)            // 164096 -> 1 CTA/SM
#define NCH    (KDIM / KCH)                  // 32 chunks

// ---------------- scratch --------------------------------------------------
// xg layout is t-major: xg[t][b][gate_perm]
__device__ __half g_xgates[(size_t)NROWS * GDIM];         // 512 MB fp16
__device__ float g_c[NTRAJ * HDIM];
__device__ __half g_h16[2][NTRAJ * HDIM];                 // fp16 h, ping-pong
__device__ __half g_x16[(size_t)NROWS * KDIM];            // fp16 x (128 MB)
__device__ __half g_wih16[(size_t)GDIM * KDIM];           // permuted fp16
__device__ __half g_whh16[(size_t)GDIM * KDIM];           // permuted fp16
__device__ float g_bias[GDIM];                            // permuted

// gate permutation: orig index go = gate*1024 + j  ->  p = (j>>3)*32 + gate*8 + (j&7)
__device__ __forceinline__ int perm_gate(int go) {
    int gate = go >> 10, j = go & 1023;
    return ((j >> 3) << 5) + (gate << 3) + (j & 7);
}

// ---------------- PTX helpers ---------------------------------------------
__device__ __forceinline__ uint32_t smem_u32(const void* p) {
    uint32_t a;
    asm("{ .reg .u64 t; cvta.to.shared.u64 t, %1; cvt.u32.u64 %0, t; }" : "=r"(a) : "l"(p));
    return a;
}
__device__ __forceinline__ void cp16(uint32_t dst, const void* src) {
    asm volatile("cp.async.cg.shared.global [%0], [%1], 16;" :: "r"(dst), "l"(src));
}
__device__ __forceinline__ void prefetch_l2(const void* p) {
    asm volatile("prefetch.global.L2 [%0];" :: "l"(p));
}
__device__ __forceinline__ void ldm4(uint32_t* r, uint32_t addr) {
    asm volatile("ldmatrix.sync.aligned.m8n8.x4.shared.b16 {%0,%1,%2,%3}, [%4];"
        : "=r"(r[0]), "=r"(r[1]), "=r"(r[2]), "=r"(r[3]) : "r"(addr));
}
__device__ __forceinline__ void mma_f16(float* d, const uint32_t* a, const uint32_t* b) {
    asm volatile("mma.sync.aligned.m16n8k16.row.col.f32.f16.f16.f32 "
        "{%0,%1,%2,%3}, {%4,%5,%6,%7}, {%8,%9}, {%0,%1,%2,%3};"
        : "+f"(d[0]), "+f"(d[1]), "+f"(d[2]), "+f"(d[3])
        : "r"(a[0]), "r"(a[1]), "r"(a[2]), "r"(a[3]), "r"(b[0]), "r"(b[1]));
}

#define MBARRIER_INIT(addr, cnt) \
    asm volatile("mbarrier.init.shared.b64 [%0], %1;" :: "r"(addr), "r"(cnt) : "memory")
#define MBARRIER_ARRIVE(addr) \
    asm volatile("mbarrier.arrive.shared.b64 _, [%0];" :: "r"(addr) : "memory")
#define CPASYNC_MBAR_ARRIVE(addr) \
    asm volatile("cp.async.mbarrier.arrive.noinc.shared::cta.b64 [%0];" :: "r"(addr) : "memory")

#define MBARRIER_WAIT_PARITY(addr, parity) do {                                   \
    uint32_t _m = (uint32_t)(addr); uint32_t _p = (uint32_t)(parity); uint32_t _d;\
    asm volatile("{\n\t.reg .pred p;\n\t"                                         \
        "mbarrier.try_wait.parity.acquire.cta.shared::cta.b64 p, [%1], %2;\n\t"   \
        "selp.b32 %0, 1, 0, p;\n\t}"                                              \
        : "=r"(_d) : "r"(_m), "r"(_p) : "memory");                                \
    if (!_d) {                                                                    \
        asm volatile("{\n\t.reg .pred P1;\n\t"                                    \
        "WL_%=:\n\t"                                                              \
        "mbarrier.try_wait.parity.acquire.cta.shared::cta.b64 P1, [%0], %1, 0x989680;\n\t" \
        "@P1 bra.uni WD_%=;\n\t"                                                  \
        "bra.uni WL_%=;\n\t"                                                      \
        "WD_%=:\n\t}" :: "r"(_m), "r"(_p) : "memory");                            \
    } } while (0)

__device__ __forceinline__ float sigmoidf_(float x) { return 1.0f / (1.0f + expf(-x)); }

// ---------------- warp-specialized fp16 HMMA GEMM --------------------------
// 384 threads: warps 0-7 consumers (32x64 warp tiles, CTA 128x128),
//              warps 8-11 producers (cp.async into 8-stage ring).
// FUSED=false: xg_tmajor[(m&31)*NTRAJ + (m>>5)][p] = half(sum_k A*B + bias[p])
// FUSED=true : gates = sum_k A*B + float(xg_t[b][p]); LSTM cell in epilogue,
//              fp16 h written to h_w (opposite parity buffer — no race).
template<bool FUSED>
__global__ __launch_bounds__(384, 1)
void gemm_f16(const __half* __restrict__ A, const __half* __restrict__ B,
              __half* __restrict__ C,
              const float* __restrict__ bias,
              const __half* __restrict__ addend,
              const float* __restrict__ dones, float* __restrict__ xout, int t,
              __half* __restrict__ h_w)
{
    extern __shared__ char smem[];
    const uint32_t sbase = smem_u32(smem);
    const int tid = threadIdx.x;
    const int row0 = blockIdx.y * 128;
    const int col0 = blockIdx.x * 128;

    if (tid == 0) {
        #pragma unroll
        for (int s = 0; s < STAGES; s++) {
            MBARRIER_INIT(sbase + MB_OFF + s * 16, 128);      // full: 128 producer arrivals
            MBARRIER_INIT(sbase + MB_OFF + s * 16 + 8, 256);  // empty: 256 consumer arrivals
        }
    }
    __syncthreads();

    if (tid >= 256) {
        // ---------------- producer warps ----------------
        const int ptid = tid - 256;     // 0..127: owns A row ptid and B row ptid
        const __half* srcA = A + (size_t)(row0 + ptid) * KDIM;
        const __half* srcB = B + (size_t)(col0 + ptid) * KDIM;
        const uint32_t dA = sbase + (uint32_t)(ptid * RB);
        const uint32_t dB = sbase + OFF_B + (uint32_t)(ptid * RB);
        for (int c = 0; c < NCH; c++) {
            const int s = c & (STAGES - 1);
            MBARRIER_WAIT_PARITY(sbase + MB_OFF + s * 16 + 8, ((c >> 3) & 1) ^ 1);
            const uint32_t sb = (uint32_t)s * STAGE_BYTES;
            const __half* a = srcA + c * KCH;
            const __half* b = srcB + c * KCH;
            #pragma unroll
            for (int i = 0; i < 4; i++) {
                cp16(dA + sb + i * 16, a + i * 8);
                cp16(dB + sb + i * 16, b + i * 8);
            }
            CPASYNC_MBAR_ARRIVE(sbase + MB_OFF + s * 16);
        }
        return;
    }

    // ---------------- consumer warps ----------------
    const int wid = tid >> 5, lane = tid & 31;
    const int wr = wid & 3, wc = wid >> 2;

    const int g = lane >> 3, r8 = lane & 7;
    const uint32_t a_off = (uint32_t)((wr * 32 + (g & 1) * 8 + r8) * RB + (g >> 1) * 16);
    const uint32_t b_off = (uint32_t)((wc * 64 + (g >> 1) * 8 + r8) * RB + (g & 1) * 16);
    const int qr = lane >> 2, qc = (lane & 3) * 2;

    if (FUSED) {
        #pragma unroll
        for (int mi = 0; mi < 2; mi++)
            #pragma unroll
            for (int rr = 0; rr < 2; rr++) {
                const int b = row0 + wr * 32 + mi * 16 + qr + rr * 8;
                prefetch_l2(addend + (size_t)b * GDIM + col0 + wc * 64);
            }
    }

    float acc[2][8][4];
    #pragma unroll
    for (int mi = 0; mi < 2; mi++)
        #pragma unroll
        for (int ni = 0; ni < 8; ni++)
            #pragma unroll
            for (int q = 0; q < 4; q++) acc[mi][ni][q] = 0.0f;

    for (int c = 0; c < NCH; c++) {
        const int s = c & (STAGES - 1);
        MBARRIER_WAIT_PARITY(sbase + MB_OFF + s * 16, (c >> 3) & 1);
        const uint32_t sb = sbase + (uint32_t)s * STAGE_BYTES;
        #pragma unroll
        for (int kk = 0; kk < 2; kk++) {
            uint32_t af[2][4];
            #pragma unroll
            for (int mi = 0; mi < 2; mi++)
                ldm4(af[mi], sb + a_off + mi * 16 * RB + kk * 32);
            uint32_t bf[8][2];
            #pragma unroll
            for (int nj = 0; nj < 4; nj++) {
                uint32_t t4[4];
                ldm4(t4, sb + OFF_B + b_off + nj * 16 * RB + kk * 32);
                bf[2 * nj][0] = t4[0]; bf[2 * nj][1] = t4[1];
                bf[2 * nj + 1][0] = t4[2]; bf[2 * nj + 1][1] = t4[3];
            }
            #pragma unroll
            for (int mi = 0; mi < 2; mi++)
                #pragma unroll
                for (int ni = 0; ni < 8; ni++)
                    mma_f16(acc[mi][ni], af[mi], bf[ni]);
        }
        // MMAs consumed the frags -> LDSM reads complete -> stage reusable
        MBARRIER_ARRIVE(sbase + MB_OFF + s * 16 + 8);
    }

    if (!FUSED) {
        // ---- plain epilogue: + bias, write fp16 to t-major xg ----
        #pragma unroll
        for (int mi = 0; mi < 2; mi++) {
            #pragma unroll
            for (int rr = 0; rr < 2; rr++) {
                const int m = row0 + wr * 32 + mi * 16 + qr + rr * 8;
                const size_t orow = (size_t)((m & 31) * NTRAJ + (m >> 5)) * GDIM;
                #pragma unroll
                for (int ni = 0; ni < 8; ni++) {
                    const int col = col0 + wc * 64 + ni * 8 + qc;
                    *(__half2*)(C + orow + col) = __floats2half2_rn(
                        acc[mi][ni][rr * 2 + 0] + bias[col],
                        acc[mi][ni][rr * 2 + 1] + bias[col + 1]);
                }
            }
        }
    } else {
        // ---- fused LSTM cell epilogue (fp16 t-major addend; fp16 h out) ----
        #pragma unroll
        for (int mi = 0; mi < 2; mi++) {
            #pragma unroll
            for (int rr = 0; rr < 2; rr++) {
                const int b = row0 + wr * 32 + mi * 16 + qr + rr * 8;
                const float keep = (t == 0) ? 1.0f : (1.0f - dones[b * T_ROLL + t - 1]);
                const float maskn = (dones[b * T_ROLL + t] != 0.0f) ? 0.0f : 1.0f;
                const __half* xrow = addend + (size_t)b * GDIM;
                #pragma unroll
                for (int jb = 0; jb < 2; jb++) {
                    const int colb = col0 + wc * 64 + jb * 32;       // gate-0 col base
                    const int j = (colb >> 2) + qc;                  // global j
                    float2 xi = __half22float2(*(const __half2*)(xrow + colb + qc));
                    float2 xf = __half22float2(*(const __half2*)(xrow + colb + 8 + qc));
                    float2 xg = __half22float2(*(const __half2*)(xrow + colb + 16 + qc));
                    float2 xo = __half22float2(*(const __half2*)(xrow + colb + 24 + qc));
                    float2 cp = *(const float2*)(g_c + b * HDIM + j);
                    float hv[2], cv[2];
                    #pragma unroll
                    for (int jj = 0; jj < 2; jj++) {
                        float gi = acc[mi][jb * 4 + 0][rr * 2 + jj] + (jj ? xi.y : xi.x);
                        float gf = acc[mi][jb * 4 + 1][rr * 2 + jj] + (jj ? xf.y : xf.x);
                        float gg = acc[mi][jb * 4 + 2][rr * 2 + jj] + (jj ? xg.y : xg.x);
                        float go = acc[mi][jb * 4 + 3][rr * 2 + jj] + (jj ? xo.y : xo.x);
                        float iv = sigmoidf_(gi);
                        float fv = sigmoidf_(gf);
                        float gv = tanhf(gg);
                        float ov = sigmoidf_(go);
                        float cn = fv * ((jj ? cp.y : cp.x) * keep) + iv * gv;
                        cv[jj] = cn;
                        hv[jj] = ov * tanhf(cn);
                    }
                    *(float2*)(g_c + b * HDIM + j) = make_float2(cv[0], cv[1]);
                    *(float2*)(xout + ((size_t)b * T_ROLL + t) * HDIM + j) =
                        make_float2(hv[0], hv[1]);
                    *(__half2*)(h_w + b * HDIM + j) =
                        __floats2half2_rn(hv[0] * maskn, hv[1] * maskn);
                }
            }
        }
    }
}

// ---------------- prep kernels ---------------------------------------------
__global__ void cvt_x_f16(const float* __restrict__ in, __half* __restrict__ out)
{
    size_t idx = ((size_t)blockIdx.x * blockDim.x + threadIdx.x) * 4;
    float4 v = *(const float4*)(in + idx);
    __half2* op = (__half2*)(out + idx);
    op[0] = __floats2half2_rn(v.x, v.y);
    op[1] = __floats2half2_rn(v.z, v.w);
}

// weight cvt with gate-row permutation: out row p = perm(go)
__global__ void cvt_w_f16(const float* __restrict__ in, __half* __restrict__ out)
{
    size_t idx = ((size_t)blockIdx.x * blockDim.x + threadIdx.x) * 4;
    int go = (int)(idx >> 10);
    int k  = (int)(idx & 1023);
    float4 v = *(const float4*)(in + idx);
    __half2* op = (__half2*)(out + (size_t)perm_gate(go) * KDIM + k);
    op[0] = __floats2half2_rn(v.x, v.y);
    op[1] = __floats2half2_rn(v.z, v.w);
}

__global__ void bias_combine(const float* __restrict__ a, const float* __restrict__ b)
{
    int i = blockIdx.x * blockDim.x + threadIdx.x;
    g_bias[perm_gate(i)] = a[i] + b[i];
}

__global__ void init_states(const float* __restrict__ rnn)
{
    int idx = blockIdx.x * blockDim.x + threadIdx.x;
    int b = idx >> 10, j = idx & 1023;
    g_c[idx] = rnn[b * 2 * HDIM + HDIM + j];
    g_h16[0][idx] = __float2half(rnn[b * 2 * HDIM + j]);
}

__global__ void write_states(const float* __restrict__ xout, float* __restrict__ out)
{
    int idx = blockIdx.x * blockDim.x + threadIdx.x;
    int b = idx >> 10, j = idx & 1023;
    out[b * 2 * HDIM + j] = xout[((size_t)b * T_ROLL + T_ROLL - 1) * HDIM + j];
    out[b * 2 * HDIM + HDIM + j] = g_c[idx];
}

// ---------------- launch ---------------------------------------------------
extern "C" void kernel_launch(void* const* d_in, const int* in_sizes, int n_in,
                              void* d_out, int out_size)
{
    const float* head  = (const float*)d_in[0];
    const float* rnn   = (const float*)d_in[1];
    const float* dones = (const float*)d_in[2];
    const float* wih   = (const float*)d_in[3];
    const float* whh   = (const float*)d_in[4];
    const float* bih   = (const float*)d_in[5];
    const float* bhh   = (const float*)d_in[6];
    float* out = (float*)d_out;

    static bool attr_set = false;
    if (!attr_set) {
        cudaFuncSetAttribute(gemm_f16<false>, cudaFuncAttributeMaxDynamicSharedMemorySize, SMEM_TOTAL);
        cudaFuncSetAttribute(gemm_f16<true>,  cudaFuncAttributeMaxDynamicSharedMemorySize, SMEM_TOTAL);
        attr_set = true;
    }

    float* bptr;
    __half *xg, *x16, *wih16, *whh16, *h0, *h1;
    cudaGetSymbolAddress((void**)&xg, g_xgates);
    cudaGetSymbolAddress((void**)&bptr, g_bias);
    cudaGetSymbolAddress((void**)&x16, g_x16);
    cudaGetSymbolAddress((void**)&wih16, g_wih16);
    cudaGetSymbolAddress((void**)&whh16, g_whh16);
    cudaGetSymbolAddress((void**)&h0, g_h16);
    h1 = h0 + (size_t)NTRAJ * HDIM;

    // Launch order keeps the profiler's sampled slot on the big GEMM.
    bias_combine<<<GDIM / 256, 256>>>(bih, bhh);
    cvt_x_f16<<<(size_t)NROWS * KDIM / 1024, 256>>>(head, x16);
    cvt_w_f16<<<(size_t)GDIM * KDIM / 1024, 256>>>(wih, wih16);

    // xg[t][b][p] = half(X @ Wih_perm^T + bias_perm)   (t-major layout)
    gemm_f16<false><<<dim3(GDIM / 128, NROWS / 128), 384, SMEM_TOTAL>>>(
        x16, wih16, xg, bptr, nullptr, nullptr, nullptr, 0, nullptr);

    cvt_w_f16<<<(size_t)GDIM * KDIM / 1024, 256>>>(whh, whh16);
    init_states<<<(NTRAJ * HDIM) / 256, 256>>>(rnn);

    for (int t = 0; t < T_ROLL; t++) {
        __half* rh = (t & 1) ? h1 : h0;
        __half* wh = (t & 1) ? h0 : h1;
        // gates = (masked h) @ Whh_perm^T + xg[t]; LSTM cell fused in epilogue
        gemm_f16<true><<<dim3(GDIM / 128, NTRAJ / 128), 384, SMEM_TOTAL>>>(
            rh, whh16, nullptr, nullptr,
            xg + (size_t)t * NTRAJ * GDIM,
            dones, out, t, wh);
    }

    write_states<<<(NTRAJ * HDIM) / 256, 256>>>(out, out + (size_t)NROWS * HDIM);
}

// round 15
// speedup vs baseline: 1.6571x; 1.6571x over previous
#include <cuda_runtime.h>
#include <cuda_fp16.h>
#include <cstdint>

#define T_ROLL 32
#define HDIM   1024
#define GDIM   4096
#define NTRAJ  2048
#define NROWS  65536
#define KDIM   1024

#define STAGES 4
#define KCH    32                  // k halves per chunk
#define RB     80                  // smem row stride bytes (32 fp16 = 64B + 16 pad)
#define OP_BYTES (128 * RB)        // 10240
#define OFF_B  OP_BYTES
#define STAGE_BYTES (2 * OP_BYTES)           // 20480
#define SMEM_TOTAL (STAGES * STAGE_BYTES)    // 81920 -> 2 CTAs/SM
#define NCH    (KDIM / KCH)                  // 32 chunks

// ---------------- scratch --------------------------------------------------
// xg layout is t-major: xg[t][traj][gate_perm]
__device__ __half g_xgates[(size_t)NROWS * GDIM];         // 512 MB fp16
__device__ float g_c[NTRAJ * HDIM];
__device__ __half g_h16[2][NTRAJ * HDIM];                 // fp16 h, ping-pong
__device__ __half g_x16[(size_t)NROWS * KDIM];            // fp16 x (128 MB)
__device__ __half g_wih16[(size_t)GDIM * KDIM];           // permuted fp16
__device__ __half g_whh16[(size_t)GDIM * KDIM];           // permuted fp16
__device__ float g_bias[GDIM];                            // permuted

// gate permutation: orig index go = gate*1024 + j  ->  p = (j>>3)*32 + gate*8 + (j&7)
__device__ __forceinline__ int perm_gate(int go) {
    int gate = go >> 10, j = go & 1023;
    return ((j >> 3) << 5) + (gate << 3) + (j & 7);
}

// ---------------- PTX helpers ---------------------------------------------
__device__ __forceinline__ uint32_t smem_u32(const void* p) {
    uint32_t a;
    asm("{ .reg .u64 t; cvta.to.shared.u64 t, %1; cvt.u32.u64 %0, t; }" : "=r"(a) : "l"(p));
    return a;
}
__device__ __forceinline__ void cp16(uint32_t dst, const void* src) {
    asm volatile("cp.async.cg.shared.global [%0], [%1], 16;" :: "r"(dst), "l"(src));
}
__device__ __forceinline__ void cp_commit() {
    asm volatile("cp.async.commit_group;" ::: "memory");
}
__device__ __forceinline__ void prefetch_l2(const void* p) {
    asm volatile("prefetch.global.L2 [%0];" :: "l"(p));
}
__device__ __forceinline__ void ldm4(uint32_t* r, uint32_t addr) {
    asm volatile("ldmatrix.sync.aligned.m8n8.x4.shared.b16 {%0,%1,%2,%3}, [%4];"
        : "=r"(r[0]), "=r"(r[1]), "=r"(r[2]), "=r"(r[3]) : "r"(addr));
}
__device__ __forceinline__ void mma_f16(float* d, const uint32_t* a, const uint32_t* b) {
    asm volatile("mma.sync.aligned.m16n8k16.row.col.f32.f16.f16.f32 "
        "{%0,%1,%2,%3}, {%4,%5,%6,%7}, {%8,%9}, {%0,%1,%2,%3};"
        : "+f"(d[0]), "+f"(d[1]), "+f"(d[2]), "+f"(d[3])
        : "r"(a[0]), "r"(a[1]), "r"(a[2]), "r"(a[3]), "r"(b[0]), "r"(b[1]));
}

__device__ __forceinline__ float sigmoidf_(float x) { return 1.0f / (1.0f + expf(-x)); }

// ---------------- fp16 HMMA GEMM (optionally fused LSTM cell) --------------
// 256 threads, 8 warps in 4x2 (32x64 warp tiles); CTA tile 128x128.
// A rows indexed with aStride (elements): supports the per-t strided big GEMM.
// FUSED=false: C[m][p] = half(sum_k A*B + bias[p])   (m = traj, C = xg chunk t)
// FUSED=true : gates = sum_k A*B + float(xg_t[b][p]); LSTM cell in epilogue,
//              fp16 h written to h_w (opposite parity buffer — no race).
template<bool FUSED>
__global__ __launch_bounds__(256, 2)
void gemm_f16(const __half* __restrict__ A, long long aStride,
              const __half* __restrict__ B,
              __half* __restrict__ C,
              const float* __restrict__ bias,
              const __half* __restrict__ addend,
              const float* __restrict__ dones, float* __restrict__ xout, int t,
              __half* __restrict__ h_w)
{
    extern __shared__ char smem[];
    const uint32_t sbase = smem_u32(smem);
    const int tid = threadIdx.x;
    const int wid = tid >> 5, lane = tid & 31;
    const int wr = wid & 3, wc = wid >> 2;
    const int row0 = blockIdx.y * 128;
    const int col0 = blockIdx.x * 128;

    // copy slot: thread covers 32B of one row per operand per chunk
    const int crow = tid >> 1;        // 0..127
    const int cq   = tid & 1;         // which 32B half of the 64B row

    const int g = lane >> 3, r8 = lane & 7;
    const uint32_t a_off = (uint32_t)((wr * 32 + (g & 1) * 8 + r8) * RB + (g >> 1) * 16);
    const uint32_t b_off = (uint32_t)((wc * 64 + (g >> 1) * 8 + r8) * RB + (g & 1) * 16);

    const int qr = lane >> 2, qc = (lane & 3) * 2;

    if (FUSED) {
        #pragma unroll
        for (int mi = 0; mi < 2; mi++)
            #pragma unroll
            for (int rr = 0; rr < 2; rr++) {
                const int b = row0 + wr * 32 + mi * 16 + qr + rr * 8;
                prefetch_l2(addend + (size_t)b * GDIM + col0 + wc * 64);
            }
    }

    float acc[2][8][4];
    #pragma unroll
    for (int mi = 0; mi < 2; mi++)
        #pragma unroll
        for (int ni = 0; ni < 8; ni++)
            #pragma unroll
            for (int q = 0; q < 4; q++) acc[mi][ni][q] = 0.0f;

    auto issue = [&](int c) {
        const uint32_t sb = sbase + (uint32_t)(c & (STAGES - 1)) * STAGE_BYTES;
        const int kc = c * KCH;
        const uint32_t dA = sb + (uint32_t)(crow * RB + cq * 32);
        const __half* sA = A + (size_t)(row0 + crow) * aStride + kc + cq * 16;
        cp16(dA, sA);
        cp16(dA + 16, sA + 8);
        const uint32_t dB = sb + OFF_B + (uint32_t)(crow * RB + cq * 32);
        const __half* sB = B + (size_t)(col0 + crow) * KDIM + kc + cq * 16;
        cp16(dB, sB);
        cp16(dB + 16, sB + 8);
    };

    #pragma unroll
    for (int s = 0; s < STAGES - 1; s++) { issue(s); cp_commit(); }

    for (int c = 0; c < NCH; c++) {
        asm volatile("cp.async.wait_group %0;" :: "n"(STAGES - 2));
        __syncthreads();

        const int p = c + STAGES - 1;
        if (p < NCH) issue(p);
        cp_commit();

        const uint32_t sb = sbase + (uint32_t)(c & (STAGES - 1)) * STAGE_BYTES;
        #pragma unroll
        for (int kk = 0; kk < 2; kk++) {
            uint32_t af[2][4];
            #pragma unroll
            for (int mi = 0; mi < 2; mi++)
                ldm4(af[mi], sb + a_off + mi * 16 * RB + kk * 32);
            uint32_t bf[8][2];
            #pragma unroll
            for (int nj = 0; nj < 4; nj++) {
                uint32_t t4[4];
                ldm4(t4, sb + OFF_B + b_off + nj * 16 * RB + kk * 32);
                bf[2 * nj][0] = t4[0]; bf[2 * nj][1] = t4[1];
                bf[2 * nj + 1][0] = t4[2]; bf[2 * nj + 1][1] = t4[3];
            }
            #pragma unroll
            for (int mi = 0; mi < 2; mi++)
                #pragma unroll
                for (int ni = 0; ni < 8; ni++)
                    mma_f16(acc[mi][ni], af[mi], bf[ni]);
        }
    }

    if (!FUSED) {
        // ---- plain epilogue: + bias, write fp16 xg chunk (rows = traj) ----
        #pragma unroll
        for (int mi = 0; mi < 2; mi++) {
            #pragma unroll
            for (int rr = 0; rr < 2; rr++) {
                const int m = row0 + wr * 32 + mi * 16 + qr + rr * 8;
                const size_t orow = (size_t)m * GDIM;
                #pragma unroll
                for (int ni = 0; ni < 8; ni++) {
                    const int col = col0 + wc * 64 + ni * 8 + qc;
                    *(__half2*)(C + orow + col) = __floats2half2_rn(
                        acc[mi][ni][rr * 2 + 0] + bias[col],
                        acc[mi][ni][rr * 2 + 1] + bias[col + 1]);
                }
            }
        }
    } else {
        // ---- fused LSTM cell epilogue (fp16 t-major addend; fp16 h out) ----
        #pragma unroll
        for (int mi = 0; mi < 2; mi++) {
            #pragma unroll
            for (int rr = 0; rr < 2; rr++) {
                const int b = row0 + wr * 32 + mi * 16 + qr + rr * 8;
                const float keep = (t == 0) ? 1.0f : (1.0f - dones[b * T_ROLL + t - 1]);
                const float maskn = (dones[b * T_ROLL + t] != 0.0f) ? 0.0f : 1.0f;
                const __half* xrow = addend + (size_t)b * GDIM;
                #pragma unroll
                for (int jb = 0; jb < 2; jb++) {
                    const int colb = col0 + wc * 64 + jb * 32;       // gate-0 col base
                    const int j = (colb >> 2) + qc;                  // global j
                    float2 xi = __half22float2(*(const __half2*)(xrow + colb + qc));
                    float2 xf = __half22float2(*(const __half2*)(xrow + colb + 8 + qc));
                    float2 xg = __half22float2(*(const __half2*)(xrow + colb + 16 + qc));
                    float2 xo = __half22float2(*(const __half2*)(xrow + colb + 24 + qc));
                    float2 cp = *(const float2*)(g_c + b * HDIM + j);
                    float hv[2], cv[2];
                    #pragma unroll
                    for (int jj = 0; jj < 2; jj++) {
                        float gi = acc[mi][jb * 4 + 0][rr * 2 + jj] + (jj ? xi.y : xi.x);
                        float gf = acc[mi][jb * 4 + 1][rr * 2 + jj] + (jj ? xf.y : xf.x);
                        float gg = acc[mi][jb * 4 + 2][rr * 2 + jj] + (jj ? xg.y : xg.x);
                        float go = acc[mi][jb * 4 + 3][rr * 2 + jj] + (jj ? xo.y : xo.x);
                        float iv = sigmoidf_(gi);
                        float fv = sigmoidf_(gf);
                        float gv = tanhf(gg);
                        float ov = sigmoidf_(go);
                        float cn = fv * ((jj ? cp.y : cp.x) * keep) + iv * gv;
                        cv[jj] = cn;
                        hv[jj] = ov * tanhf(cn);
                    }
                    *(float2*)(g_c + b * HDIM + j) = make_float2(cv[0], cv[1]);
                    *(float2*)(xout + ((size_t)b * T_ROLL + t) * HDIM + j) =
                        make_float2(hv[0], hv[1]);
                    *(__half2*)(h_w + b * HDIM + j) =
                        __floats2half2_rn(hv[0] * maskn, hv[1] * maskn);
                }
            }
        }
    }
}

// ---------------- prep kernels ---------------------------------------------
__global__ void cvt_x_f16(const float* __restrict__ in, __half* __restrict__ out)
{
    size_t idx = ((size_t)blockIdx.x * blockDim.x + threadIdx.x) * 4;
    float4 v = *(const float4*)(in + idx);
    __half2* op = (__half2*)(out + idx);
    op[0] = __floats2half2_rn(v.x, v.y);
    op[1] = __floats2half2_rn(v.z, v.w);
}

// weight cvt with gate-row permutation: out row p = perm(go)
__global__ void cvt_w_f16(const float* __restrict__ in, __half* __restrict__ out)
{
    size_t idx = ((size_t)blockIdx.x * blockDim.x + threadIdx.x) * 4;
    int go = (int)(idx >> 10);
    int k  = (int)(idx & 1023);
    float4 v = *(const float4*)(in + idx);
    __half2* op = (__half2*)(out + (size_t)perm_gate(go) * KDIM + k);
    op[0] = __floats2half2_rn(v.x, v.y);
    op[1] = __floats2half2_rn(v.z, v.w);
}

__global__ void bias_combine(const float* __restrict__ a, const float* __restrict__ b)
{
    int i = blockIdx.x * blockDim.x + threadIdx.x;
    g_bias[perm_gate(i)] = a[i] + b[i];
}

__global__ void init_states(const float* __restrict__ rnn)
{
    int idx = blockIdx.x * blockDim.x + threadIdx.x;
    int b = idx >> 10, j = idx & 1023;
    g_c[idx] = rnn[b * 2 * HDIM + HDIM + j];
    g_h16[0][idx] = __float2half(rnn[b * 2 * HDIM + j]);
}

__global__ void write_states(const float* __restrict__ xout, float* __restrict__ out)
{
    int idx = blockIdx.x * blockDim.x + threadIdx.x;
    int b = idx >> 10, j = idx & 1023;
    out[b * 2 * HDIM + j] = xout[((size_t)b * T_ROLL + T_ROLL - 1) * HDIM + j];
    out[b * 2 * HDIM + HDIM + j] = g_c[idx];
}

// ---------------- launch ---------------------------------------------------
extern "C" void kernel_launch(void* const* d_in, const int* in_sizes, int n_in,
                              void* d_out, int out_size)
{
    const float* head  = (const float*)d_in[0];
    const float* rnn   = (const float*)d_in[1];
    const float* dones = (const float*)d_in[2];
    const float* wih   = (const float*)d_in[3];
    const float* whh   = (const float*)d_in[4];
    const float* bih   = (const float*)d_in[5];
    const float* bhh   = (const float*)d_in[6];
    float* out = (float*)d_out;

    static cudaStream_t sA = nullptr;
    static cudaEvent_t evPrep = nullptr, ev[T_ROLL];
    static bool init_done = false;
    if (!init_done) {
        cudaFuncSetAttribute(gemm_f16<false>, cudaFuncAttributeMaxDynamicSharedMemorySize, SMEM_TOTAL);
        cudaFuncSetAttribute(gemm_f16<true>,  cudaFuncAttributeMaxDynamicSharedMemorySize, SMEM_TOTAL);
        cudaStreamCreateWithFlags(&sA, cudaStreamNonBlocking);
        cudaEventCreateWithFlags(&evPrep, cudaEventDisableTiming);
        for (int i = 0; i < T_ROLL; i++)
            cudaEventCreateWithFlags(&ev[i], cudaEventDisableTiming);
        init_done = true;
    }

    float* bptr;
    __half *xg, *x16, *wih16, *whh16, *h0, *h1;
    cudaGetSymbolAddress((void**)&xg, g_xgates);
    cudaGetSymbolAddress((void**)&bptr, g_bias);
    cudaGetSymbolAddress((void**)&x16, g_x16);
    cudaGetSymbolAddress((void**)&wih16, g_wih16);
    cudaGetSymbolAddress((void**)&whh16, g_whh16);
    cudaGetSymbolAddress((void**)&h0, g_h16);
    h1 = h0 + (size_t)NTRAJ * HDIM;

    const dim3 gemm_grid(GDIM / 128, NTRAJ / 128);

    // ---- prep on the main (capture) stream ----
    bias_combine<<<GDIM / 256, 256>>>(bih, bhh);
    cvt_x_f16<<<(size_t)NROWS * KDIM / 1024, 256>>>(head, x16);
    cvt_w_f16<<<(size_t)GDIM * KDIM / 1024, 256>>>(wih, wih16);
    cudaEventRecord(evPrep, 0);

    // ---- big GEMM split per-t, on stream A (fork) ----
    cudaStreamWaitEvent(sA, evPrep, 0);
    for (int t = 0; t < T_ROLL; t++) {
        // xg[t][traj][p] = half(x[traj*32+t] @ Wih_perm^T + bias_perm)
        gemm_f16<false><<<gemm_grid, 256, SMEM_TOTAL, sA>>>(
            x16 + (size_t)t * KDIM, (long long)T_ROLL * KDIM,
            wih16, xg + (size_t)t * NTRAJ * GDIM, bptr,
            nullptr, nullptr, nullptr, 0, nullptr);
        cudaEventRecord(ev[t], sA);
    }

    cvt_w_f16<<<(size_t)GDIM * KDIM / 1024, 256>>>(whh, whh16);
    init_states<<<(NTRAJ * HDIM) / 256, 256>>>(rnn);

    // ---- step chain on the main stream, gated per-t on the xg chunk ----
    for (int t = 0; t < T_ROLL; t++) {
        __half* rh = (t & 1) ? h1 : h0;
        __half* wh = (t & 1) ? h0 : h1;
        cudaStreamWaitEvent(0, ev[t], 0);
        // gates = (masked h) @ Whh_perm^T + xg[t]; LSTM cell fused in epilogue
        gemm_f16<true><<<gemm_grid, 256, SMEM_TOTAL>>>(
            rh, (long long)KDIM, whh16, nullptr, nullptr,
            xg + (size_t)t * NTRAJ * GDIM,
            dones, out, t, wh);
    }

    write_states<<<(NTRAJ * HDIM) / 256, 256>>>(out, out + (size_t)NROWS * HDIM);
}

// round 17
// speedup vs baseline: 1.6584x; 1.0008x over previous
#include <cuda_runtime.h>
#include <cuda_fp16.h>
#include <cstdint>

#define T_ROLL 32
#define HDIM   1024
#define GDIM   4096
#define NTRAJ  2048
#define NROWS  65536
#define KDIM   1024

#define STAGES 4
#define KCH    32                  // k halves per chunk
#define RB     80                  // smem row stride bytes (32 fp16 = 64B + 16 pad)
#define OP_BYTES (128 * RB)        // 10240
#define OFF_B  OP_BYTES
#define STAGE_BYTES (2 * OP_BYTES)           // 20480
#define SMEM_TOTAL (STAGES * STAGE_BYTES)    // 81920 -> 2 CTAs/SM
#define NCH    (KDIM / KCH)                  // 32 chunks

// ---------------- scratch --------------------------------------------------
// xg layout is t-major: xg[t][traj][gate_perm]
__device__ __half g_xgates[(size_t)NROWS * GDIM];         // 512 MB fp16
__device__ float g_c[NTRAJ * HDIM];
__device__ __half g_h16[2][NTRAJ * HDIM];                 // fp16 h, ping-pong
__device__ __half g_x16[(size_t)NROWS * KDIM];            // fp16 x (128 MB)
__device__ __half g_wih16[(size_t)GDIM * KDIM];           // permuted fp16
__device__ __half g_whh16[(size_t)GDIM * KDIM];           // permuted fp16
__device__ float g_bias[GDIM];                            // permuted

// gate permutation: orig index go = gate*1024 + j  ->  p = (j>>3)*32 + gate*8 + (j&7)
__device__ __forceinline__ int perm_gate(int go) {
    int gate = go >> 10, j = go & 1023;
    return ((j >> 3) << 5) + (gate << 3) + (j & 7);
}

// ---------------- PTX helpers ---------------------------------------------
__device__ __forceinline__ uint32_t smem_u32(const void* p) {
    uint32_t a;
    asm("{ .reg .u64 t; cvta.to.shared.u64 t, %1; cvt.u32.u64 %0, t; }" : "=r"(a) : "l"(p));
    return a;
}
__device__ __forceinline__ void cp16(uint32_t dst, const void* src) {
    asm volatile("cp.async.cg.shared.global [%0], [%1], 16;" :: "r"(dst), "l"(src));
}
__device__ __forceinline__ void cp_commit() {
    asm volatile("cp.async.commit_group;" ::: "memory");
}
__device__ __forceinline__ void prefetch_l2(const void* p) {
    asm volatile("prefetch.global.L2 [%0];" :: "l"(p));
}
__device__ __forceinline__ void ldm4(uint32_t* r, uint32_t addr) {
    asm volatile("ldmatrix.sync.aligned.m8n8.x4.shared.b16 {%0,%1,%2,%3}, [%4];"
        : "=r"(r[0]), "=r"(r[1]), "=r"(r[2]), "=r"(r[3]) : "r"(addr));
}
__device__ __forceinline__ void mma_f16(float* d, const uint32_t* a, const uint32_t* b) {
    asm volatile("mma.sync.aligned.m16n8k16.row.col.f32.f16.f16.f32 "
        "{%0,%1,%2,%3}, {%4,%5,%6,%7}, {%8,%9}, {%0,%1,%2,%3};"
        : "+f"(d[0]), "+f"(d[1]), "+f"(d[2]), "+f"(d[3])
        : "r"(a[0]), "r"(a[1]), "r"(a[2]), "r"(a[3]), "r"(b[0]), "r"(b[1]));
}

__device__ __forceinline__ float sigmoidf_(float x) { return 1.0f / (1.0f + expf(-x)); }

// ---------------- fp16 HMMA GEMM (optionally fused LSTM cell) --------------
// 256 threads, 8 warps in 4x2 (32x64 warp tiles); CTA tile 128x128.
// A rows indexed with aStride (elements): supports the per-t strided big GEMM.
// FUSED=false: C[m][p] = half(sum_k A*B + bias[p])   (m = traj, C = xg chunk t)
// FUSED=true : gates = sum_k A*B + float(xg_t[b][p]); LSTM cell in epilogue,
//              fp16 h written to h_w (opposite parity buffer — no race).
//              If state_out != nullptr (t == 31): also write h,c to rnn states.
template<bool FUSED>
__global__ __launch_bounds__(256, 2)
void gemm_f16(const __half* __restrict__ A, long long aStride,
              const __half* __restrict__ B,
              __half* __restrict__ C,
              const float* __restrict__ bias,
              const __half* __restrict__ addend,
              const float* __restrict__ dones, float* __restrict__ xout, int t,
              __half* __restrict__ h_w, float* __restrict__ state_out)
{
    extern __shared__ char smem[];
    const uint32_t sbase = smem_u32(smem);
    const int tid = threadIdx.x;
    const int wid = tid >> 5, lane = tid & 31;
    const int wr = wid & 3, wc = wid >> 2;
    const int row0 = blockIdx.y * 128;
    const int col0 = blockIdx.x * 128;

    // copy slot: thread covers 32B of one row per operand per chunk
    const int crow = tid >> 1;        // 0..127
    const int cq   = tid & 1;         // which 32B half of the 64B row

    const int g = lane >> 3, r8 = lane & 7;
    const uint32_t a_off = (uint32_t)((wr * 32 + (g & 1) * 8 + r8) * RB + (g >> 1) * 16);
    const uint32_t b_off = (uint32_t)((wc * 64 + (g >> 1) * 8 + r8) * RB + (g & 1) * 16);

    const int qr = lane >> 2, qc = (lane & 3) * 2;

    if (FUSED) {
        #pragma unroll
        for (int mi = 0; mi < 2; mi++)
            #pragma unroll
            for (int rr = 0; rr < 2; rr++) {
                const int b = row0 + wr * 32 + mi * 16 + qr + rr * 8;
                prefetch_l2(addend + (size_t)b * GDIM + col0 + wc * 64);
            }
    }

    float acc[2][8][4];
    #pragma unroll
    for (int mi = 0; mi < 2; mi++)
        #pragma unroll
        for (int ni = 0; ni < 8; ni++)
            #pragma unroll
            for (int q = 0; q < 4; q++) acc[mi][ni][q] = 0.0f;

    auto issue = [&](int c) {
        const uint32_t sb = sbase + (uint32_t)(c & (STAGES - 1)) * STAGE_BYTES;
        const int kc = c * KCH;
        const uint32_t dA = sb + (uint32_t)(crow * RB + cq * 32);
        const __half* sA = A + (size_t)(row0 + crow) * aStride + kc + cq * 16;
        cp16(dA, sA);
        cp16(dA + 16, sA + 8);
        const uint32_t dB = sb + OFF_B + (uint32_t)(crow * RB + cq * 32);
        const __half* sB = B + (size_t)(col0 + crow) * KDIM + kc + cq * 16;
        cp16(dB, sB);
        cp16(dB + 16, sB + 8);
    };

    #pragma unroll
    for (int s = 0; s < STAGES - 1; s++) { issue(s); cp_commit(); }

    for (int c = 0; c < NCH; c++) {
        asm volatile("cp.async.wait_group %0;" :: "n"(STAGES - 2));
        __syncthreads();

        const int p = c + STAGES - 1;
        if (p < NCH) issue(p);
        cp_commit();

        const uint32_t sb = sbase + (uint32_t)(c & (STAGES - 1)) * STAGE_BYTES;
        #pragma unroll
        for (int kk = 0; kk < 2; kk++) {
            uint32_t af[2][4];
            #pragma unroll
            for (int mi = 0; mi < 2; mi++)
                ldm4(af[mi], sb + a_off + mi * 16 * RB + kk * 32);
            uint32_t bf[8][2];
            #pragma unroll
            for (int nj = 0; nj < 4; nj++) {
                uint32_t t4[4];
                ldm4(t4, sb + OFF_B + b_off + nj * 16 * RB + kk * 32);
                bf[2 * nj][0] = t4[0]; bf[2 * nj][1] = t4[1];
                bf[2 * nj + 1][0] = t4[2]; bf[2 * nj + 1][1] = t4[3];
            }
            #pragma unroll
            for (int mi = 0; mi < 2; mi++)
                #pragma unroll
                for (int ni = 0; ni < 8; ni++)
                    mma_f16(acc[mi][ni], af[mi], bf[ni]);
        }
    }

    if (!FUSED) {
        // ---- plain epilogue: + bias, write fp16 xg chunk (rows = traj) ----
        #pragma unroll
        for (int mi = 0; mi < 2; mi++) {
            #pragma unroll
            for (int rr = 0; rr < 2; rr++) {
                const int m = row0 + wr * 32 + mi * 16 + qr + rr * 8;
                const size_t orow = (size_t)m * GDIM;
                #pragma unroll
                for (int ni = 0; ni < 8; ni++) {
                    const int col = col0 + wc * 64 + ni * 8 + qc;
                    *(__half2*)(C + orow + col) = __floats2half2_rn(
                        acc[mi][ni][rr * 2 + 0] + bias[col],
                        acc[mi][ni][rr * 2 + 1] + bias[col + 1]);
                }
            }
        }
    } else {
        // ---- fused LSTM cell epilogue (fp16 t-major addend; fp16 h out) ----
        #pragma unroll
        for (int mi = 0; mi < 2; mi++) {
            #pragma unroll
            for (int rr = 0; rr < 2; rr++) {
                const int b = row0 + wr * 32 + mi * 16 + qr + rr * 8;
                const float keep = (t == 0) ? 1.0f : (1.0f - dones[b * T_ROLL + t - 1]);
                const float maskn = (dones[b * T_ROLL + t] != 0.0f) ? 0.0f : 1.0f;
                const __half* xrow = addend + (size_t)b * GDIM;
                #pragma unroll
                for (int jb = 0; jb < 2; jb++) {
                    const int colb = col0 + wc * 64 + jb * 32;       // gate-0 col base
                    const int j = (colb >> 2) + qc;                  // global j
                    float2 xi = __half22float2(*(const __half2*)(xrow + colb + qc));
                    float2 xf = __half22float2(*(const __half2*)(xrow + colb + 8 + qc));
                    float2 xg = __half22float2(*(const __half2*)(xrow + colb + 16 + qc));
                    float2 xo = __half22float2(*(const __half2*)(xrow + colb + 24 + qc));
                    float2 cp = *(const float2*)(g_c + b * HDIM + j);
                    float hv[2], cv[2];
                    #pragma unroll
                    for (int jj = 0; jj < 2; jj++) {
                        float gi = acc[mi][jb * 4 + 0][rr * 2 + jj] + (jj ? xi.y : xi.x);
                        float gf = acc[mi][jb * 4 + 1][rr * 2 + jj] + (jj ? xf.y : xf.x);
                        float gg = acc[mi][jb * 4 + 2][rr * 2 + jj] + (jj ? xg.y : xg.x);
                        float go = acc[mi][jb * 4 + 3][rr * 2 + jj] + (jj ? xo.y : xo.x);
                        float iv = sigmoidf_(gi);
                        float fv = sigmoidf_(gf);
                        float gv = tanhf(gg);
                        float ov = sigmoidf_(go);
                        float cn = fv * ((jj ? cp.y : cp.x) * keep) + iv * gv;
                        cv[jj] = cn;
                        hv[jj] = ov * tanhf(cn);
                    }
                    *(float2*)(g_c + b * HDIM + j) = make_float2(cv[0], cv[1]);
                    *(float2*)(xout + ((size_t)b * T_ROLL + t) * HDIM + j) =
                        make_float2(hv[0], hv[1]);
                    *(__half2*)(h_w + b * HDIM + j) =
                        __floats2half2_rn(hv[0] * maskn, hv[1] * maskn);
                    if (state_out != nullptr) {
                        // final step: new_rnn_states = [h | c]
                        *(float2*)(state_out + (size_t)b * 2 * HDIM + j) =
                            make_float2(hv[0], hv[1]);
                        *(float2*)(state_out + (size_t)b * 2 * HDIM + HDIM + j) =
                            make_float2(cv[0], cv[1]);
                    }
                }
            }
        }
    }
}

// ---------------- prep kernels ---------------------------------------------
__global__ void cvt_x_f16(const float* __restrict__ in, __half* __restrict__ out)
{
    size_t idx = ((size_t)blockIdx.x * blockDim.x + threadIdx.x) * 4;
    float4 v = *(const float4*)(in + idx);
    __half2* op = (__half2*)(out + idx);
    op[0] = __floats2half2_rn(v.x, v.y);
    op[1] = __floats2half2_rn(v.z, v.w);
}

// weight cvt with gate-row permutation: out row p = perm(go)
__global__ void cvt_w_f16(const float* __restrict__ in, __half* __restrict__ out)
{
    size_t idx = ((size_t)blockIdx.x * blockDim.x + threadIdx.x) * 4;
    int go = (int)(idx >> 10);
    int k  = (int)(idx & 1023);
    float4 v = *(const float4*)(in + idx);
    __half2* op = (__half2*)(out + (size_t)perm_gate(go) * KDIM + k);
    op[0] = __floats2half2_rn(v.x, v.y);
    op[1] = __floats2half2_rn(v.z, v.w);
}

__global__ void bias_combine(const float* __restrict__ a, const float* __restrict__ b)
{
    int i = blockIdx.x * blockDim.x + threadIdx.x;
    g_bias[perm_gate(i)] = a[i] + b[i];
}

__global__ void init_states(const float* __restrict__ rnn)
{
    int idx = blockIdx.x * blockDim.x + threadIdx.x;
    int b = idx >> 10, j = idx & 1023;
    g_c[idx] = rnn[b * 2 * HDIM + HDIM + j];
    g_h16[0][idx] = __float2half(rnn[b * 2 * HDIM + j]);
}

// ---------------- launch ---------------------------------------------------
extern "C" void kernel_launch(void* const* d_in, const int* in_sizes, int n_in,
                              void* d_out, int out_size)
{
    const float* head  = (const float*)d_in[0];
    const float* rnn   = (const float*)d_in[1];
    const float* dones = (const float*)d_in[2];
    const float* wih   = (const float*)d_in[3];
    const float* whh   = (const float*)d_in[4];
    const float* bih   = (const float*)d_in[5];
    const float* bhh   = (const float*)d_in[6];
    float* out = (float*)d_out;

    static cudaStream_t sA = nullptr;
    static cudaEvent_t evPrep = nullptr, ev[T_ROLL];
    static bool init_done = false;
    if (!init_done) {
        cudaFuncSetAttribute(gemm_f16<false>, cudaFuncAttributeMaxDynamicSharedMemorySize, SMEM_TOTAL);
        cudaFuncSetAttribute(gemm_f16<true>,  cudaFuncAttributeMaxDynamicSharedMemorySize, SMEM_TOTAL);
        cudaStreamCreateWithFlags(&sA, cudaStreamNonBlocking);
        cudaEventCreateWithFlags(&evPrep, cudaEventDisableTiming);
        for (int i = 0; i < T_ROLL; i++)
            cudaEventCreateWithFlags(&ev[i], cudaEventDisableTiming);
        init_done = true;
    }

    float* bptr;
    __half *xg, *x16, *wih16, *whh16, *h0, *h1;
    cudaGetSymbolAddress((void**)&xg, g_xgates);
    cudaGetSymbolAddress((void**)&bptr, g_bias);
    cudaGetSymbolAddress((void**)&x16, g_x16);
    cudaGetSymbolAddress((void**)&wih16, g_wih16);
    cudaGetSymbolAddress((void**)&whh16, g_whh16);
    cudaGetSymbolAddress((void**)&h0, g_h16);
    h1 = h0 + (size_t)NTRAJ * HDIM;

    const dim3 gemm_grid(GDIM / 128, NTRAJ / 128);

    // ---- prep on the main (capture) stream ----
    bias_combine<<<GDIM / 256, 256>>>(bih, bhh);
    cvt_x_f16<<<(size_t)NROWS * KDIM / 1024, 256>>>(head, x16);
    cvt_w_f16<<<(size_t)GDIM * KDIM / 1024, 256>>>(wih, wih16);
    cudaEventRecord(evPrep, 0);

    // ---- big GEMM split per-t, on stream A (fork) ----
    cudaStreamWaitEvent(sA, evPrep, 0);
    for (int t = 0; t < T_ROLL; t++) {
        // xg[t][traj][p] = half(x[traj*32+t] @ Wih_perm^T + bias_perm)
        gemm_f16<false><<<gemm_grid, 256, SMEM_TOTAL, sA>>>(
            x16 + (size_t)t * KDIM, (long long)T_ROLL * KDIM,
            wih16, xg + (size_t)t * NTRAJ * GDIM, bptr,
            nullptr, nullptr, nullptr, 0, nullptr, nullptr);
        cudaEventRecord(ev[t], sA);
    }

    cvt_w_f16<<<(size_t)GDIM * KDIM / 1024, 256>>>(whh, whh16);
    init_states<<<(NTRAJ * HDIM) / 256, 256>>>(rnn);

    // ---- step chain on the main stream, gated per-t on the xg chunk ----
    float* state_out = out + (size_t)NROWS * HDIM;
    for (int t = 0; t < T_ROLL; t++) {
        __half* rh = (t & 1) ? h1 : h0;
        __half* wh = (t & 1) ? h0 : h1;
        cudaStreamWaitEvent(0, ev[t], 0);
        // gates = (masked h) @ Whh_perm^T + xg[t]; LSTM cell fused in epilogue;
        // final step also writes new_rnn_states directly.
        gemm_f16<true><<<gemm_grid, 256, SMEM_TOTAL>>>(
            rh, (long long)KDIM, whh16, nullptr, nullptr,
            xg + (size_t)t * NTRAJ * GDIM,
            dones, out, t, wh,
            (t == T_ROLL - 1) ? state_out : nullptr);
    }
}